// round 11
// baseline (speedup 1.0000x reference)
#include <cuda_runtime.h>
#include <cuda_fp16.h>
#include <cstdint>

#define N_TOK   131072
#define DIM     64
#define NE      1024
#define DECAYF  0.99f
#define ONE_M_D 0.01f
#define EPSF    1e-5f

// ---- output layout (reference return order, flattened, float32) ----
#define O_Q     0
#define O_DIFF  (O_Q + N_TOK*DIM)
#define O_IND   (O_DIFF + 1)
#define O_NEMB  (O_IND + N_TOK)
#define O_NCS   (O_NEMB + DIM*NE)
#define O_NEA   (O_NCS + NE)

// ---- device-global scratch ----
__device__ float  g_enorm[NE];
__device__ float  g_embedT[NE*DIM];   // exact fp32 codebook [NE][64]
__device__ __half g_eT_hi[NE*DIM];    // fp16 codebook [NE][64]
__device__ float  g_count[NE];
__device__ float  g_embed_sum[NE*DIM];// [NE][64] row-major (for float4 atomics)
__device__ double g_diff_acc;
__device__ float  g_n;
__device__ int    g_emax_i;           // max ||e||^2 as float bits (positive)

__device__ __forceinline__ uint32_t smem_u32(const void* p) {
    uint32_t a;
    asm("{ .reg .u64 t; cvta.to.shared.u64 t, %1; cvt.u32.u64 %0, t; }" : "=r"(a) : "l"(p));
    return a;
}
__device__ __forceinline__ void ldsm4(uint32_t& r0, uint32_t& r1, uint32_t& r2, uint32_t& r3,
                                      uint32_t addr) {
    asm volatile("ldmatrix.sync.aligned.m8n8.x4.shared.b16 {%0,%1,%2,%3}, [%4];"
                 : "=r"(r0), "=r"(r1), "=r"(r2), "=r"(r3) : "r"(addr));
}
__device__ __forceinline__ void mma16816(float* c, const uint32_t* a, uint32_t b0, uint32_t b1) {
    asm volatile("mma.sync.aligned.m16n8k16.row.col.f32.f16.f16.f32 "
                 "{%0,%1,%2,%3},{%4,%5,%6,%7},{%8,%9},{%0,%1,%2,%3};"
                 : "+f"(c[0]), "+f"(c[1]), "+f"(c[2]), "+f"(c[3])
                 : "r"(a[0]), "r"(a[1]), "r"(a[2]), "r"(a[3]), "r"(b0), "r"(b1));
}
#define CP_ASYNC16(dst, src) \
    asm volatile("cp.async.cg.shared.global [%0], [%1], 16;" :: "r"(dst), "l"(src) : "memory")
#define CP_COMMIT() asm volatile("cp.async.commit_group;" ::: "memory")
#define CP_WAIT0()  asm volatile("cp.async.wait_group 0;" ::: "memory")

// =====================================================================
// prep A: transpose codebook + fp16 + zero scratch (grid 64x256)
// =====================================================================
__global__ void vq_prep_a(const float* __restrict__ embed) {
    int gid = blockIdx.x * blockDim.x + threadIdx.x;   // float4 units over [64][1024]
    float4 v = ((const float4*)embed)[gid];
    int idx = gid * 4;
    int d = idx >> 10;
    int j = idx & 1023;
    float vv[4] = {v.x, v.y, v.z, v.w};
    #pragma unroll
    for (int i = 0; i < 4; ++i) {
        int o = (j + i) * DIM + d;
        g_embedT[o] = vv[i];
        g_eT_hi[o] = __float2half_rn(vv[i]);
    }
    ((float4*)g_embed_sum)[gid] = make_float4(0.f, 0.f, 0.f, 0.f);
    if (gid < NE) g_count[gid] = 0.f;
    if (gid == 0) { g_diff_acc = 0.0; g_emax_i = 0; }
}

// =====================================================================
// prep B: exact ||e_j||^2 + max norm (grid 128x256, warp per codeword)
// =====================================================================
__global__ void vq_prep_b() {
    int t = blockIdx.x * blockDim.x + threadIdx.x;
    int w = t >> 5, lane = t & 31;
    float2 v = *(const float2*)(g_embedT + w * DIM + lane * 2);
    float s = v.x * v.x + v.y * v.y;
    #pragma unroll
    for (int off = 16; off > 0; off >>= 1)
        s += __shfl_xor_sync(0xFFFFFFFFu, s, off);
    if (lane == 0) {
        g_enorm[w] = s;
        atomicMax(&g_emax_i, __float_as_int(s));   // positive floats: int order == float order
    }
}

// =====================================================================
// MAIN: fp16 HMMA (A fragments hoisted to registers) + per-lane top2
//       + margin-filtered exact rescore + float4 segment atomics
//   128 tokens/CTA; 8 iters x 2 chunks of 64 codes; warps 4(M) x 2(N)
//   smem: Ah 16K | B0 16K | B1 16K | enorm 4K | sd 8K | sj 8K = 68K
// =====================================================================
#define SA_H   0
#define SB(b)  (16384 + (b)*16384)
#define SEN    49152
#define SD_OFF 53248
#define SJ_OFF 61440
#define SMEM_MAIN 69632

__global__ void __launch_bounds__(256, 2) vq_main(const float* __restrict__ x,
                                                  float* __restrict__ out) {
    extern __shared__ char smc[];
    const uint32_t sb = smem_u32(smc);
    float* enorm_s = (float*)(smc + SEN);
    float* sd = (float*)(smc + SD_OFF);      // [128][16] approx dists
    int*   sj = (int*)(smc + SJ_OFF);        // [128][16] candidate indices
    __shared__ float s_diff;

    const int tid  = threadIdx.x;
    const int wid  = tid >> 5;
    const int lane = tid & 31;
    const int bm   = blockIdx.x * 128;
    const int wm   = (wid >> 1) * 32;     // warp M offset
    const int wn   = (wid & 1) * 32;      // warp N offset within 64-chunk
    const int g    = lane >> 2;
    const int tq   = lane & 3;
    const int sub  = lane >> 3;
    const int l7   = lane & 7;

    if (tid == 0) s_diff = 0.f;
    ((float4*)enorm_s)[tid] = ((const float4*)g_enorm)[tid];

    // ---- build A (x tile, fp16) in smem, swizzled: addr = m*128 + ((c^(m&7))<<4)
    #pragma unroll
    for (int p = 0; p < 4; ++p) {
        int task = tid + p * 256;          // 1024 tasks: (row m, chunk c)
        int m = task >> 3, c = task & 7;
        const float4* xr = (const float4*)(x + (size_t)(bm + m) * DIM + c * 8);
        float4 v0 = xr[0], v1 = xr[1];
        float f[8] = {v0.x, v0.y, v0.z, v0.w, v1.x, v1.y, v1.z, v1.w};
        __half hh[8];
        #pragma unroll
        for (int i = 0; i < 8; ++i) hh[i] = __float2half_rn(f[i]);
        *(uint4*)(smc + SA_H + m * 128 + ((c ^ (m & 7)) << 4)) = *(const uint4*)hh;
    }

    // ---- cp.async loader: 2 chunks (128 codes) per call ----
    auto load_B2 = [&](int it, int buf) {
        const int jb = it * 128;
        #pragma unroll
        for (int p = 0; p < 4; ++p) {
            int task = tid + p * 256;      // 1024 tasks: (code j 0..127, c 0..7)
            int j = task >> 3, c = task & 7;
            uint32_t dst = sb + SB(buf) + (uint32_t)(j * 128 + ((c ^ (j & 7)) << 4));
            const char* src = (const char*)g_eT_hi + (size_t)(jb + j) * 128 + c * 16;
            CP_ASYNC16(dst, src);
        }
        CP_COMMIT();
    };
    load_B2(0, 0);

    // ---- ldmatrix lane addressing ----
    int rowA[2], rA7[2];
    #pragma unroll
    for (int mt = 0; mt < 2; ++mt) {
        int r = wm + mt * 16 + ((sub & 1) << 3) + l7;
        rowA[mt] = r * 128; rA7[mt] = r & 7;
    }
    const int subhiA = sub >> 1;
    int rowB[2], rB7[2];
    #pragma unroll
    for (int np = 0; np < 2; ++np) {
        int r = wn + np * 16 + ((sub >> 1) << 3) + l7;
        rowB[np] = r * 128; rB7[np] = r & 7;
    }
    const int subloB = sub & 1;

    // ---- hoist A fragments into registers (reused for ALL 16 chunks) ----
    __syncthreads();   // A stores visible
    uint32_t afrag[2][4][4];   // [mt][ks][reg]
    #pragma unroll
    for (int ks = 0; ks < 4; ++ks) {
        #pragma unroll
        for (int mt = 0; mt < 2; ++mt) {
            uint32_t o = (uint32_t)(rowA[mt] + (((ks * 2 + subhiA) ^ rA7[mt]) << 4));
            ldsm4(afrag[mt][ks][0], afrag[mt][ks][1], afrag[mt][ks][2], afrag[mt][ks][3],
                  sb + SA_H + o);
        }
    }

    // per-row-slot top2 over this lane's disjoint 128-code subset
    float d1[4], d2[4];
    int   i1[4], i2[4];
    #pragma unroll
    for (int s = 0; s < 4; ++s) { d1[s] = d2[s] = 3.402823466e+38f; i1[s] = i2[s] = 0; }

    for (int it = 0; it < 8; ++it) {
        const int buf = it & 1;
        CP_WAIT0();
        __syncthreads();               // B[buf] ready; prev consumers done
        if (it < 7) load_B2(it + 1, buf ^ 1);

        #pragma unroll
        for (int sc = 0; sc < 2; ++sc) {
            const int ch = it * 2 + sc;
            const uint32_t bbase = sb + SB(buf) + sc * 8192;

            float acc[2][4][4];
            #pragma unroll
            for (int mt = 0; mt < 2; ++mt)
                #pragma unroll
                for (int nt = 0; nt < 4; ++nt)
                    #pragma unroll
                    for (int q = 0; q < 4; ++q) acc[mt][nt][q] = 0.f;

            #pragma unroll
            for (int ks = 0; ks < 4; ++ks) {
                uint32_t bh[2][4];
                #pragma unroll
                for (int np = 0; np < 2; ++np) {
                    uint32_t o = (uint32_t)(rowB[np] + (((ks * 2 + subloB) ^ rB7[np]) << 4));
                    ldsm4(bh[np][0], bh[np][1], bh[np][2], bh[np][3], bbase + o);
                }
                #pragma unroll
                for (int mt = 0; mt < 2; ++mt)
                    #pragma unroll
                    for (int np = 0; np < 2; ++np) {
                        mma16816(acc[mt][np*2+0], afrag[mt][ks], bh[np][0], bh[np][1]);
                        mma16816(acc[mt][np*2+1], afrag[mt][ks], bh[np][2], bh[np][3]);
                    }
            }

            // ---- dist ~= enorm - 2*dot_hi, per-lane top2 ----
            #pragma unroll
            for (int nt = 0; nt < 4; ++nt) {
                int col0 = ch * 64 + wn + nt * 8 + tq * 2;
                float2 en = *(const float2*)(enorm_s + col0);
                #pragma unroll
                for (int mt = 0; mt < 2; ++mt) {
                    #pragma unroll
                    for (int rh = 0; rh < 2; ++rh) {
                        int s = mt * 2 + rh;
                        float dv0 = fmaf(-2.f, acc[mt][nt][rh*2+0], en.x);
                        float dv1 = fmaf(-2.f, acc[mt][nt][rh*2+1], en.y);
                        if (dv0 < d1[s]) { d2[s]=d1[s]; i2[s]=i1[s]; d1[s]=dv0; i1[s]=col0; }
                        else if (dv0 < d2[s]) { d2[s]=dv0; i2[s]=col0; }
                        if (dv1 < d1[s]) { d2[s]=d1[s]; i2[s]=i1[s]; d1[s]=dv1; i1[s]=col0+1; }
                        else if (dv1 < d2[s]) { d2[s]=dv1; i2[s]=col0+1; }
                    }
                }
            }
        }
    }

    // ---- write 16 (dist, idx) candidates per token ----
    __syncthreads();
    {
        const int half = wid & 1;
        const int cbase = (half * 4 + tq) * 2;
        #pragma unroll
        for (int s = 0; s < 4; ++s) {
            int row = wm + (s >> 1) * 16 + (s & 1) * 8 + g;
            sd[row * 16 + cbase + 0] = d1[s];
            sd[row * 16 + cbase + 1] = d2[s];
            sj[row * 16 + cbase + 0] = i1[s];
            sj[row * 16 + cbase + 1] = i2[s];
        }
    }
    __syncthreads();

    // ======== epilogue: 2 threads per token, cooperative halves ========
    {
        const int tk   = tid >> 1;
        const int half = tid & 1;
        const int token = bm + tk;
        const unsigned pmask = 3u << (lane & 30);   // this pair's shfl mask
        float xv[32];
        float xnh = 0.f;
        {
            const float4* xr = (const float4*)(x + (size_t)token * DIM + half * 32);
            #pragma unroll
            for (int i = 0; i < 8; ++i) {
                float4 v = xr[i];
                xv[4*i] = v.x; xv[4*i+1] = v.y; xv[4*i+2] = v.z; xv[4*i+3] = v.w;
                xnh += v.x*v.x + v.y*v.y + v.z*v.z + v.w*v.w;
            }
        }
        float xn = xnh + __shfl_xor_sync(pmask, xnh, 1);
        // margin: |dist_err| <= 2^-9 * ||x|| * ||e||  (fp16 bound), + slack
        float dmin = 3.402823466e+38f;
        #pragma unroll
        for (int c = 0; c < 16; ++c) dmin = fminf(dmin, sd[tk * 16 + c]);
        float emax = __int_as_float(g_emax_i);
        float thresh = dmin + 4.4e-3f * sqrtf(xn * emax) + 1e-3f;

        float bd = 3.402823466e+38f; int bi = 0x7FFFFFFF;
        #pragma unroll 1
        for (int c = 0; c < 16; ++c) {
            float dc = sd[tk * 16 + c];
            if (dc > thresh) continue;            // pair-uniform decision
            int j = sj[tk * 16 + c];
            const float4* er = (const float4*)(g_embedT + (size_t)j * DIM + half * 32);
            float s0 = 0.f, s1 = 0.f, s2 = 0.f, s3 = 0.f;
            #pragma unroll
            for (int i = 0; i < 8; ++i) {
                float4 e = er[i];
                s0 = fmaf(e.x, xv[4*i],   s0);
                s1 = fmaf(e.y, xv[4*i+1], s1);
                s2 = fmaf(e.z, xv[4*i+2], s2);
                s3 = fmaf(e.w, xv[4*i+3], s3);
            }
            float part = (s0 + s1) + (s2 + s3);
            float full = part + __shfl_xor_sync(pmask, part, 1);
            float de = fmaf(-2.f, full, enorm_s[j]);
            if (de < bd || (de == bd && j < bi)) { bd = de; bi = j; }
        }
        const int ind = bi;
        if (half == 0) {
            out[O_IND + token] = (float)ind;
            atomicAdd(&g_count[ind], 1.0f);
        }

        // quantize write + diff + vectorized embed_sum atomics (own 32-dim half)
        const float4* qr = (const float4*)(g_embedT + (size_t)ind * DIM + half * 32);
        float4* esrow = (float4*)(g_embed_sum + (size_t)ind * DIM + half * 32);
        float dsum = 0.f;
        #pragma unroll
        for (int i = 0; i < 8; ++i) {
            float4 q = qr[i];
            int kb = half * 32 + 4 * i;
            *(float4*)(out + O_Q + (size_t)token * DIM + kb) = q;
            float e0 = q.x - xv[4*i],   e1 = q.y - xv[4*i+1];
            float e2 = q.z - xv[4*i+2], e3 = q.w - xv[4*i+3];
            dsum += e0*e0 + e1*e1 + e2*e2 + e3*e3;
            atomicAdd(esrow + i, make_float4(xv[4*i], xv[4*i+1], xv[4*i+2], xv[4*i+3]));
        }
        #pragma unroll
        for (int off = 16; off > 0; off >>= 1)
            dsum += __shfl_xor_sync(0xFFFFFFFFu, dsum, off);
        if ((tid & 31) == 0) atomicAdd(&s_diff, dsum);
    }
    __syncthreads();
    if (tid == 0) atomicAdd(&g_diff_acc, (double)s_diff);
}

// =====================================================================
// finalize A: cluster-size EMA + n reduction + diff (1 block)
// =====================================================================
__global__ void vq_fin_a(const float* __restrict__ cluster_size,
                         float* __restrict__ out) {
    __shared__ float sr[NE];
    int j = threadIdx.x;
    float ncs = cluster_size[j] * DECAYF + ONE_M_D * g_count[j];
    out[O_NCS + j] = ncs;
    sr[j] = ncs;
    __syncthreads();
    for (int s = 512; s > 0; s >>= 1) {
        if (j < s) sr[j] += sr[j + s];
        __syncthreads();
    }
    if (j == 0) {
        g_n = sr[0];
        out[O_DIFF] = (float)(g_diff_acc * (1.0 / (double)((size_t)N_TOK * DIM)));
    }
}

// =====================================================================
// finalize B: embed-avg EMA + normalized embed (grid 64x256)
//   g_embed_sum is [NE][64]; outputs remain [64][NE]
// =====================================================================
__global__ void vq_fin_b(const float* __restrict__ embed_avg,
                         float* __restrict__ out) {
    int gid = blockIdx.x * blockDim.x + threadIdx.x;
    int idx = gid * 4;
    int d = idx >> 10;
    int j = idx & 1023;
    float4 ea = ((const float4*)embed_avg)[gid];
    float es0 = g_embed_sum[(size_t)(j + 0) * DIM + d];
    float es1 = g_embed_sum[(size_t)(j + 1) * DIM + d];
    float es2 = g_embed_sum[(size_t)(j + 2) * DIM + d];
    float es3 = g_embed_sum[(size_t)(j + 3) * DIM + d];
    float4 nea;
    nea.x = ea.x * DECAYF + ONE_M_D * es0;
    nea.y = ea.y * DECAYF + ONE_M_D * es1;
    nea.z = ea.z * DECAYF + ONE_M_D * es2;
    nea.w = ea.w * DECAYF + ONE_M_D * es3;
    float n = g_n;
    float denom = n + (float)NE * EPSF;
    float c0 = (out[O_NCS + j + 0] + EPSF) / denom * n;
    float c1 = (out[O_NCS + j + 1] + EPSF) / denom * n;
    float c2 = (out[O_NCS + j + 2] + EPSF) / denom * n;
    float c3 = (out[O_NCS + j + 3] + EPSF) / denom * n;
    out[O_NEA + idx + 0] = nea.x;
    out[O_NEA + idx + 1] = nea.y;
    out[O_NEA + idx + 2] = nea.z;
    out[O_NEA + idx + 3] = nea.w;
    out[O_NEMB + idx + 0] = nea.x / c0;
    out[O_NEMB + idx + 1] = nea.y / c1;
    out[O_NEMB + idx + 2] = nea.z / c2;
    out[O_NEMB + idx + 3] = nea.w / c3;
}

extern "C" void kernel_launch(void* const* d_in, const int* in_sizes, int n_in,
                              void* d_out, int out_size) {
    const float* x            = (const float*)d_in[0];
    const float* embed        = (const float*)d_in[1];
    const float* cluster_size = (const float*)d_in[2];
    const float* embed_avg    = (const float*)d_in[3];
    float* out = (float*)d_out;

    cudaFuncSetAttribute(vq_main, cudaFuncAttributeMaxDynamicSharedMemorySize, SMEM_MAIN);

    vq_prep_a<<<64, 256>>>(embed);
    vq_prep_b<<<128, 256>>>();
    vq_main<<<N_TOK / 128, 256, SMEM_MAIN>>>(x, out);
    vq_fin_a<<<1, NE>>>(cluster_size, out);
    vq_fin_b<<<64, 256>>>(embed_avg, out);
}

// round 12
// speedup vs baseline: 1.5404x; 1.5404x over previous
#include <cuda_runtime.h>
#include <cuda_fp16.h>
#include <cstdint>

#define N_TOK   131072
#define DIM     64
#define NE      1024
#define DECAYF  0.99f
#define ONE_M_D 0.01f
#define EPSF    1e-5f

// ---- output layout (reference return order, flattened, float32) ----
#define O_Q     0
#define O_DIFF  (O_Q + N_TOK*DIM)
#define O_IND   (O_DIFF + 1)
#define O_NEMB  (O_IND + N_TOK)
#define O_NCS   (O_NEMB + DIM*NE)
#define O_NEA   (O_NCS + NE)

// ---- device-global scratch ----
__device__ float  g_enorm[NE];
__device__ float  g_embedT[NE*DIM];   // exact fp32 codebook [NE][64]
__device__ __half g_eT_hi[NE*DIM];    // fp16 codebook [NE][64]
__device__ float  g_count[NE];
__device__ float  g_embed_sum[NE*DIM];// [NE][64] row-major (for float4 atomics)
__device__ double g_diff_acc;
__device__ float  g_n;
__device__ int    g_emax_i;           // max ||e||^2 as float bits (positive)

__device__ __forceinline__ uint32_t smem_u32(const void* p) {
    uint32_t a;
    asm("{ .reg .u64 t; cvta.to.shared.u64 t, %1; cvt.u32.u64 %0, t; }" : "=r"(a) : "l"(p));
    return a;
}
__device__ __forceinline__ void ldsm4(uint32_t& r0, uint32_t& r1, uint32_t& r2, uint32_t& r3,
                                      uint32_t addr) {
    asm volatile("ldmatrix.sync.aligned.m8n8.x4.shared.b16 {%0,%1,%2,%3}, [%4];"
                 : "=r"(r0), "=r"(r1), "=r"(r2), "=r"(r3) : "r"(addr));
}
__device__ __forceinline__ void mma16816(float* c, const uint32_t* a, uint32_t b0, uint32_t b1) {
    asm volatile("mma.sync.aligned.m16n8k16.row.col.f32.f16.f16.f32 "
                 "{%0,%1,%2,%3},{%4,%5,%6,%7},{%8,%9},{%0,%1,%2,%3};"
                 : "+f"(c[0]), "+f"(c[1]), "+f"(c[2]), "+f"(c[3])
                 : "r"(a[0]), "r"(a[1]), "r"(a[2]), "r"(a[3]), "r"(b0), "r"(b1));
}
#define CP_ASYNC16(dst, src) \
    asm volatile("cp.async.cg.shared.global [%0], [%1], 16;" :: "r"(dst), "l"(src) : "memory")
#define CP_COMMIT() asm volatile("cp.async.commit_group;" ::: "memory")
#define CP_WAIT0()  asm volatile("cp.async.wait_group 0;" ::: "memory")

// pack candidate index into low 10 mantissa bits of dist (one LOP3)
__device__ __forceinline__ float pack_key(float d, int j) {
    return __uint_as_float((__float_as_uint(d) & 0xFFFFFC00u) | (uint32_t)j);
}

// =====================================================================
// prep A: transpose codebook + fp16 + zero scratch (grid 64x256)
// =====================================================================
__global__ void vq_prep_a(const float* __restrict__ embed) {
    int gid = blockIdx.x * blockDim.x + threadIdx.x;   // float4 units over [64][1024]
    float4 v = ((const float4*)embed)[gid];
    int idx = gid * 4;
    int d = idx >> 10;
    int j = idx & 1023;
    float vv[4] = {v.x, v.y, v.z, v.w};
    #pragma unroll
    for (int i = 0; i < 4; ++i) {
        int o = (j + i) * DIM + d;
        g_embedT[o] = vv[i];
        g_eT_hi[o] = __float2half_rn(vv[i]);
    }
    ((float4*)g_embed_sum)[gid] = make_float4(0.f, 0.f, 0.f, 0.f);
    if (gid < NE) g_count[gid] = 0.f;
    if (gid == 0) { g_diff_acc = 0.0; g_emax_i = 0; }
}

// =====================================================================
// prep B: exact ||e_j||^2 + max norm (grid 128x256, warp per codeword)
// =====================================================================
__global__ void vq_prep_b() {
    int t = blockIdx.x * blockDim.x + threadIdx.x;
    int w = t >> 5, lane = t & 31;
    float2 v = *(const float2*)(g_embedT + w * DIM + lane * 2);
    float s = v.x * v.x + v.y * v.y;
    #pragma unroll
    for (int off = 16; off > 0; off >>= 1)
        s += __shfl_xor_sync(0xFFFFFFFFu, s, off);
    if (lane == 0) {
        g_enorm[w] = s;
        atomicMax(&g_emax_i, __float_as_int(s));   // positive floats: int order == float order
    }
}

// =====================================================================
// MAIN: fp16 HMMA (A frags in regs) + branchless packed-key top2
//       + margin-filtered exact rescore + float4 segment atomics
//   128 tokens/CTA; 8 iters x 2 chunks of 64 codes; warps 4(M) x 2(N)
//   smem: Ah 16K | B0 16K | B1 16K | enorm 4K | sd 8K = 60K
// =====================================================================
#define SA_H   0
#define SB(b)  (16384 + (b)*16384)
#define SEN    49152
#define SD_OFF 53248
#define SMEM_MAIN 61440

__global__ void __launch_bounds__(256, 2) vq_main(const float* __restrict__ x,
                                                  float* __restrict__ out) {
    extern __shared__ char smc[];
    const uint32_t sb = smem_u32(smc);
    float* enorm_s = (float*)(smc + SEN);
    float* sd = (float*)(smc + SD_OFF);      // [128][16] packed (dist|idx) keys
    __shared__ float s_diff;

    const int tid  = threadIdx.x;
    const int wid  = tid >> 5;
    const int lane = tid & 31;
    const int bm   = blockIdx.x * 128;
    const int wm   = (wid >> 1) * 32;     // warp M offset
    const int wn   = (wid & 1) * 32;      // warp N offset within 64-chunk
    const int g    = lane >> 2;
    const int tq   = lane & 3;
    const int sub  = lane >> 3;
    const int l7   = lane & 7;

    if (tid == 0) s_diff = 0.f;
    ((float4*)enorm_s)[tid] = ((const float4*)g_enorm)[tid];

    // ---- build A (x tile, fp16) in smem, swizzled: addr = m*128 + ((c^(m&7))<<4)
    #pragma unroll
    for (int p = 0; p < 4; ++p) {
        int task = tid + p * 256;          // 1024 tasks: (row m, chunk c)
        int m = task >> 3, c = task & 7;
        const float4* xr = (const float4*)(x + (size_t)(bm + m) * DIM + c * 8);
        float4 v0 = xr[0], v1 = xr[1];
        float f[8] = {v0.x, v0.y, v0.z, v0.w, v1.x, v1.y, v1.z, v1.w};
        __half hh[8];
        #pragma unroll
        for (int i = 0; i < 8; ++i) hh[i] = __float2half_rn(f[i]);
        *(uint4*)(smc + SA_H + m * 128 + ((c ^ (m & 7)) << 4)) = *(const uint4*)hh;
    }

    // ---- cp.async loader: 2 chunks (128 codes) per call ----
    auto load_B2 = [&](int it, int buf) {
        const int jb = it * 128;
        #pragma unroll
        for (int p = 0; p < 4; ++p) {
            int task = tid + p * 256;      // 1024 tasks: (code j 0..127, c 0..7)
            int j = task >> 3, c = task & 7;
            uint32_t dst = sb + SB(buf) + (uint32_t)(j * 128 + ((c ^ (j & 7)) << 4));
            const char* src = (const char*)g_eT_hi + (size_t)(jb + j) * 128 + c * 16;
            CP_ASYNC16(dst, src);
        }
        CP_COMMIT();
    };
    load_B2(0, 0);

    // ---- ldmatrix lane addressing ----
    int rowA[2], rA7[2];
    #pragma unroll
    for (int mt = 0; mt < 2; ++mt) {
        int r = wm + mt * 16 + ((sub & 1) << 3) + l7;
        rowA[mt] = r * 128; rA7[mt] = r & 7;
    }
    const int subhiA = sub >> 1;
    int rowB[2], rB7[2];
    #pragma unroll
    for (int np = 0; np < 2; ++np) {
        int r = wn + np * 16 + ((sub >> 1) << 3) + l7;
        rowB[np] = r * 128; rB7[np] = r & 7;
    }
    const int subloB = sub & 1;

    // ---- hoist A fragments into registers (reused for ALL 16 chunks) ----
    __syncthreads();   // A stores visible
    uint32_t afrag[2][4][4];   // [mt][ks][reg]
    #pragma unroll
    for (int ks = 0; ks < 4; ++ks) {
        #pragma unroll
        for (int mt = 0; mt < 2; ++mt) {
            uint32_t o = (uint32_t)(rowA[mt] + (((ks * 2 + subhiA) ^ rA7[mt]) << 4));
            ldsm4(afrag[mt][ks][0], afrag[mt][ks][1], afrag[mt][ks][2], afrag[mt][ks][3],
                  sb + SA_H + o);
        }
    }

    // packed-key top2 per row-slot (indices live in key LSBs)
    float d1[4], d2[4];
    #pragma unroll
    for (int s = 0; s < 4; ++s) { d1[s] = d2[s] = 3.402823466e+38f; }

    for (int it = 0; it < 8; ++it) {
        const int buf = it & 1;
        CP_WAIT0();
        __syncthreads();               // B[buf] ready; prev consumers done
        if (it < 7) load_B2(it + 1, buf ^ 1);

        #pragma unroll
        for (int sc = 0; sc < 2; ++sc) {
            const int ch = it * 2 + sc;
            const uint32_t bbase = sb + SB(buf) + sc * 8192;

            float acc[2][4][4];
            #pragma unroll
            for (int mt = 0; mt < 2; ++mt)
                #pragma unroll
                for (int nt = 0; nt < 4; ++nt)
                    #pragma unroll
                    for (int q = 0; q < 4; ++q) acc[mt][nt][q] = 0.f;

            #pragma unroll
            for (int ks = 0; ks < 4; ++ks) {
                uint32_t bh[2][4];
                #pragma unroll
                for (int np = 0; np < 2; ++np) {
                    uint32_t o = (uint32_t)(rowB[np] + (((ks * 2 + subloB) ^ rB7[np]) << 4));
                    ldsm4(bh[np][0], bh[np][1], bh[np][2], bh[np][3], bbase + o);
                }
                #pragma unroll
                for (int mt = 0; mt < 2; ++mt)
                    #pragma unroll
                    for (int np = 0; np < 2; ++np) {
                        mma16816(acc[mt][np*2+0], afrag[mt][ks], bh[np][0], bh[np][1]);
                        mma16816(acc[mt][np*2+1], afrag[mt][ks], bh[np][2], bh[np][3]);
                    }
            }

            // ---- dist ~= enorm - 2*dot_hi; branchless packed top2 ----
            #pragma unroll
            for (int nt = 0; nt < 4; ++nt) {
                int col0 = ch * 64 + wn + nt * 8 + tq * 2;
                float2 en = *(const float2*)(enorm_s + col0);
                #pragma unroll
                for (int mt = 0; mt < 2; ++mt) {
                    #pragma unroll
                    for (int rh = 0; rh < 2; ++rh) {
                        int s = mt * 2 + rh;
                        float k0 = pack_key(fmaf(-2.f, acc[mt][nt][rh*2+0], en.x), col0);
                        float k1 = pack_key(fmaf(-2.f, acc[mt][nt][rh*2+1], en.y), col0 + 1);
                        float mx0 = fmaxf(k0, d1[s]);
                        d1[s] = fminf(k0, d1[s]);
                        d2[s] = fminf(mx0, d2[s]);
                        float mx1 = fmaxf(k1, d1[s]);
                        d1[s] = fminf(k1, d1[s]);
                        d2[s] = fminf(mx1, d2[s]);
                    }
                }
            }
        }
    }

    // ---- write 16 packed candidates per token ----
    __syncthreads();
    {
        const int half = wid & 1;
        const int cbase = (half * 4 + tq) * 2;
        #pragma unroll
        for (int s = 0; s < 4; ++s) {
            int row = wm + (s >> 1) * 16 + (s & 1) * 8 + g;
            sd[row * 16 + cbase + 0] = d1[s];
            sd[row * 16 + cbase + 1] = d2[s];
        }
    }
    __syncthreads();

    // ======== epilogue: 2 threads per token, cooperative halves ========
    {
        const int tk   = tid >> 1;
        const int half = tid & 1;
        const int token = bm + tk;
        const unsigned pmask = 3u << (lane & 30);   // this pair's shfl mask
        float xv[32];
        float xnh = 0.f;
        {
            const float4* xr = (const float4*)(x + (size_t)token * DIM + half * 32);
            #pragma unroll
            for (int i = 0; i < 8; ++i) {
                float4 v = xr[i];
                xv[4*i] = v.x; xv[4*i+1] = v.y; xv[4*i+2] = v.z; xv[4*i+3] = v.w;
                xnh += v.x*v.x + v.y*v.y + v.z*v.z + v.w*v.w;
            }
        }
        float xn = xnh + __shfl_xor_sync(pmask, xnh, 1);
        // margin: fp16 bound + key-packing noise slack
        float dmin = 3.402823466e+38f;
        #pragma unroll
        for (int c = 0; c < 16; ++c) dmin = fminf(dmin, sd[tk * 16 + c]);
        float emax = __int_as_float(g_emax_i);
        float thresh = dmin + 4.4e-3f * sqrtf(xn * emax) + 0.1f;

        float bd = 3.402823466e+38f; int bi = 0x7FFFFFFF;
        #pragma unroll 1
        for (int c = 0; c < 16; ++c) {
            float dc = sd[tk * 16 + c];
            if (dc > thresh) continue;            // pair-uniform decision
            int j = __float_as_int(dc) & 1023;
            const float4* er = (const float4*)(g_embedT + (size_t)j * DIM + half * 32);
            float s0 = 0.f, s1 = 0.f, s2 = 0.f, s3 = 0.f;
            #pragma unroll
            for (int i = 0; i < 8; ++i) {
                float4 e = er[i];
                s0 = fmaf(e.x, xv[4*i],   s0);
                s1 = fmaf(e.y, xv[4*i+1], s1);
                s2 = fmaf(e.z, xv[4*i+2], s2);
                s3 = fmaf(e.w, xv[4*i+3], s3);
            }
            float part = (s0 + s1) + (s2 + s3);
            float full = part + __shfl_xor_sync(pmask, part, 1);
            float de = fmaf(-2.f, full, enorm_s[j]);
            if (de < bd || (de == bd && j < bi)) { bd = de; bi = j; }
        }
        const int ind = bi;
        if (half == 0) {
            out[O_IND + token] = (float)ind;
            atomicAdd(&g_count[ind], 1.0f);
        }

        // quantize write + diff + vectorized embed_sum atomics (own 32-dim half)
        const float4* qr = (const float4*)(g_embedT + (size_t)ind * DIM + half * 32);
        float4* esrow = (float4*)(g_embed_sum + (size_t)ind * DIM + half * 32);
        float dsum = 0.f;
        #pragma unroll
        for (int i = 0; i < 8; ++i) {
            float4 q = qr[i];
            int kb = half * 32 + 4 * i;
            *(float4*)(out + O_Q + (size_t)token * DIM + kb) = q;
            float e0 = q.x - xv[4*i],   e1 = q.y - xv[4*i+1];
            float e2 = q.z - xv[4*i+2], e3 = q.w - xv[4*i+3];
            dsum += e0*e0 + e1*e1 + e2*e2 + e3*e3;
            atomicAdd(esrow + i, make_float4(xv[4*i], xv[4*i+1], xv[4*i+2], xv[4*i+3]));
        }
        #pragma unroll
        for (int off = 16; off > 0; off >>= 1)
            dsum += __shfl_xor_sync(0xFFFFFFFFu, dsum, off);
        if ((tid & 31) == 0) atomicAdd(&s_diff, dsum);
    }
    __syncthreads();
    if (tid == 0) atomicAdd(&g_diff_acc, (double)s_diff);
}

// =====================================================================
// finalize A: cluster-size EMA + n reduction + diff (1 block)
// =====================================================================
__global__ void vq_fin_a(const float* __restrict__ cluster_size,
                         float* __restrict__ out) {
    __shared__ float sr[NE];
    int j = threadIdx.x;
    float ncs = cluster_size[j] * DECAYF + ONE_M_D * g_count[j];
    out[O_NCS + j] = ncs;
    sr[j] = ncs;
    __syncthreads();
    for (int s = 512; s > 0; s >>= 1) {
        if (j < s) sr[j] += sr[j + s];
        __syncthreads();
    }
    if (j == 0) {
        g_n = sr[0];
        out[O_DIFF] = (float)(g_diff_acc * (1.0 / (double)((size_t)N_TOK * DIM)));
    }
}

// =====================================================================
// finalize B: embed-avg EMA + normalized embed (grid 64x256)
//   g_embed_sum is [NE][64]; outputs remain [64][NE]
// =====================================================================
__global__ void vq_fin_b(const float* __restrict__ embed_avg,
                         float* __restrict__ out) {
    int gid = blockIdx.x * blockDim.x + threadIdx.x;
    int idx = gid * 4;
    int d = idx >> 10;
    int j = idx & 1023;
    float4 ea = ((const float4*)embed_avg)[gid];
    float es0 = g_embed_sum[(size_t)(j + 0) * DIM + d];
    float es1 = g_embed_sum[(size_t)(j + 1) * DIM + d];
    float es2 = g_embed_sum[(size_t)(j + 2) * DIM + d];
    float es3 = g_embed_sum[(size_t)(j + 3) * DIM + d];
    float4 nea;
    nea.x = ea.x * DECAYF + ONE_M_D * es0;
    nea.y = ea.y * DECAYF + ONE_M_D * es1;
    nea.z = ea.z * DECAYF + ONE_M_D * es2;
    nea.w = ea.w * DECAYF + ONE_M_D * es3;
    float n = g_n;
    float denom = n + (float)NE * EPSF;
    float c0 = (out[O_NCS + j + 0] + EPSF) / denom * n;
    float c1 = (out[O_NCS + j + 1] + EPSF) / denom * n;
    float c2 = (out[O_NCS + j + 2] + EPSF) / denom * n;
    float c3 = (out[O_NCS + j + 3] + EPSF) / denom * n;
    out[O_NEA + idx + 0] = nea.x;
    out[O_NEA + idx + 1] = nea.y;
    out[O_NEA + idx + 2] = nea.z;
    out[O_NEA + idx + 3] = nea.w;
    out[O_NEMB + idx + 0] = nea.x / c0;
    out[O_NEMB + idx + 1] = nea.y / c1;
    out[O_NEMB + idx + 2] = nea.z / c2;
    out[O_NEMB + idx + 3] = nea.w / c3;
}

extern "C" void kernel_launch(void* const* d_in, const int* in_sizes, int n_in,
                              void* d_out, int out_size) {
    const float* x            = (const float*)d_in[0];
    const float* embed        = (const float*)d_in[1];
    const float* cluster_size = (const float*)d_in[2];
    const float* embed_avg    = (const float*)d_in[3];
    float* out = (float*)d_out;

    cudaFuncSetAttribute(vq_main, cudaFuncAttributeMaxDynamicSharedMemorySize, SMEM_MAIN);

    vq_prep_a<<<64, 256>>>(embed);
    vq_prep_b<<<128, 256>>>();
    vq_main<<<N_TOK / 128, 256, SMEM_MAIN>>>(x, out);
    vq_fin_a<<<1, NE>>>(cluster_size, out);
    vq_fin_b<<<64, 256>>>(embed_avg, out);
}